// round 5
// baseline (speedup 1.0000x reference)
#include <cuda_runtime.h>

#define Tt 512
#define Dd 1024
#define Ee 64
#define II 512
#define KK 4
#define NPAIR (Tt*KK)

typedef unsigned u32;
typedef unsigned long long u64;

// ---- scratch ----
__device__ int   g_cnt[Ee];
__device__ int   g_slot[Ee*Tt];
__device__ float g_topw[NPAIR];
__device__ float g_H[NPAIR*II];          // 4 MB
__device__ float g_Y[NPAIR*Dd];          // 8 MB

// X tile smem geometry: 64 rows x 64 k bf16, row stride 68 bf16 = 136 B
#define XROW 136
#define XHSZ 8704            // 64*136
#define USTR 65              // u_buf row stride (floats)

// fp32 -> bf16 hi + bf16 residual lo (packed pairs; lo16 = first elem)
__device__ __forceinline__ void cvt_hl(float vx, float vy, u32& h, u32& l){
  asm("cvt.rn.bf16x2.f32 %0, %1, %2;" : "=r"(h) : "f"(vy), "f"(vx));
  float r0 = vx - __uint_as_float(h << 16);
  float r1 = vy - __uint_as_float(h & 0xFFFF0000u);
  asm("cvt.rn.bf16x2.f32 %0, %1, %2;" : "=r"(l) : "f"(r1), "f"(r0));
}

__device__ __forceinline__ void mma16816(float* c, const u32* a, u32 b0, u32 b1){
  asm volatile(
    "mma.sync.aligned.m16n8k16.row.col.f32.bf16.bf16.f32 "
    "{%0,%1,%2,%3}, {%4,%5,%6,%7}, {%8,%9}, {%0,%1,%2,%3};"
    : "+f"(c[0]), "+f"(c[1]), "+f"(c[2]), "+f"(c[3])
    : "r"(a[0]), "r"(a[1]), "r"(a[2]), "r"(a[3]), "r"(b0), "r"(b1));
}

// load one m16k16 A fragment pair (hi/lo) straight from global fp32
__device__ __forceinline__ void load_afrag(const float* p, size_t ld, u32* ah, u32* al){
  float2 v0 = *(const float2*)(p);
  float2 v1 = *(const float2*)(p + 8*ld);
  float2 v2 = *(const float2*)(p + 8);
  float2 v3 = *(const float2*)(p + 8*ld + 8);
  cvt_hl(v0.x, v0.y, ah[0], al[0]);
  cvt_hl(v1.x, v1.y, ah[1], al[1]);
  cvt_hl(v2.x, v2.y, ah[2], al[2]);
  cvt_hl(v3.x, v3.y, ah[3], al[3]);
}

// stage 64x64 fp32 tile -> bf16 hi/lo swizzle-free smem (256 threads)
__device__ __forceinline__ void stage_x(char* dsm, const float* src, int tid){
  int r = tid >> 2, cb = (tid & 3) * 16;
  const float4* s4 = (const float4*)(src);
  char* hp = dsm + r*XROW + cb*2;
  #pragma unroll
  for (int j = 0; j < 4; j++){
    float4 v = s4[j];
    u32 h0, l0, h1, l1;
    cvt_hl(v.x, v.y, h0, l0);
    cvt_hl(v.z, v.w, h1, l1);
    *(uint2*)(hp + 8*j)        = make_uint2(h0, h1);
    *(uint2*)(hp + XHSZ + 8*j) = make_uint2(l0, l1);
  }
}

// ---- kernel 0 ----
__global__ void zero_kernel(){
  if (threadIdx.x < Ee) g_cnt[threadIdx.x] = 0;
}

// ---- kernel 1: router ----
__global__ void router_kernel(const float* __restrict__ x, const float* __restrict__ gw){
  int t = blockIdx.x;
  __shared__ float xs[Dd];
  __shared__ float lg[Ee];
  for (int i = threadIdx.x; i < Dd/4; i += 64)
    ((float4*)xs)[i] = ((const float4*)(x + (size_t)t*Dd))[i];
  __syncthreads();
  const float* w = gw + (size_t)threadIdx.x * Dd;
  float acc = 0.f;
  #pragma unroll 4
  for (int d = 0; d < Dd; d += 4){
    float4 wv = *(const float4*)(w + d);
    acc += wv.x*xs[d] + wv.y*xs[d+1] + wv.z*xs[d+2] + wv.w*xs[d+3];
  }
  lg[threadIdx.x] = acc;
  __syncthreads();
  if (threadIdx.x == 0){
    float mx = lg[0];
    for (int i = 1; i < Ee; i++) mx = fmaxf(mx, lg[i]);
    for (int i = 0; i < Ee; i++) lg[i] = __expf(lg[i] - mx);
    float wsum = 0.f; int ids[KK]; float ws[KK];
    for (int k = 0; k < KK; k++){
      int bi = 0; float bv = -1.f;
      for (int i = 0; i < Ee; i++){ float v = lg[i]; if (v > bv){ bv = v; bi = i; } }
      ids[k] = bi; ws[k] = bv; lg[bi] = -2.f; wsum += bv;
    }
    float inv = 1.f / wsum;
    for (int k = 0; k < KK; k++){
      int p = t*KK + k;
      g_topw[p] = ws[k] * inv;
      int slot = atomicAdd(&g_cnt[ids[k]], 1);
      g_slot[ids[k]*Tt + slot] = p;
    }
  }
}

// ---- kernel 2: gate+up, mma.sync bf16 split ----
// grid (Ee,4). warps 0-3: gate rows f0+w*32..+31; warps 4-7: up rows.
__global__ void __launch_bounds__(256) gateup_kernel(const float* __restrict__ x,
    const float* __restrict__ wg, const float* __restrict__ wu){
  int e = blockIdx.x;
  int nt = g_cnt[e];
  if (nt == 0) return;
  int f0 = blockIdx.y * 128;
  extern __shared__ char dsm[];           // [0,17408) X hi/lo ; epilogue: u_buf 33280B
  __shared__ int sp[64];
  int tid = threadIdx.x;
  int wid = tid >> 5, lane = tid & 31;
  int gid = lane >> 2, tig = lane & 3;
  int mrow = (wid & 3) * 32;
  const float* wA = ((wid < 4) ? wg : wu) + ((size_t)(e*II) + f0 + mrow + gid)*Dd + tig*2;

  for (int n0 = 0; n0 < nt; n0 += 64){
    int ntile = min(64, nt - n0);
    int nfr = (ntile + 7) >> 3;
    __syncthreads();
    if (tid < 64) sp[tid] = g_slot[e*Tt + ((n0 + tid < nt) ? n0 + tid : n0)];
    __syncthreads();

    float C[2][8][4];
    #pragma unroll
    for (int i = 0; i < 2; i++)
      #pragma unroll
      for (int j = 0; j < 8; j++)
        #pragma unroll
        for (int q = 0; q < 4; q++) C[i][j][q] = 0.f;

    for (int k0 = 0; k0 < Dd; k0 += 64){
      stage_x(dsm, x + (size_t)(sp[tid>>2] >> 2)*Dd + k0 + (tid&3)*16, tid);
      __syncthreads();
      #pragma unroll
      for (int ks = 0; ks < 4; ks++){
        u32 ah[2][4], al[2][4];
        const float* ap = wA + k0 + ks*16;
        load_afrag(ap,               Dd, ah[0], al[0]);
        load_afrag(ap + (size_t)16*Dd, Dd, ah[1], al[1]);
        char* xb = dsm + gid*XROW + (ks*8 + tig)*4;
        for (int j = 0; j < nfr; j++){
          char* xj = xb + j*8*XROW;
          u32 bh0 = *(u32*)(xj),          bh1 = *(u32*)(xj + 16);
          u32 bl0 = *(u32*)(xj + XHSZ),   bl1 = *(u32*)(xj + XHSZ + 16);
          #pragma unroll
          for (int i = 0; i < 2; i++){
            mma16816(C[i][j], ah[i], bh0, bh1);
            mma16816(C[i][j], al[i], bh0, bh1);
            mma16816(C[i][j], ah[i], bl0, bl1);
          }
        }
      }
      __syncthreads();
    }

    // epilogue: warps 4-7 park u in smem, warps 0-3 combine with g
    float* ub = (float*)dsm;
    if (wid >= 4){
      #pragma unroll
      for (int i = 0; i < 2; i++)
        for (int j = 0; j < nfr; j++){
          int row = (wid-4)*32 + i*16 + gid, col = j*8 + tig*2;
          ub[row*USTR + col]       = C[i][j][0];
          ub[row*USTR + col + 1]   = C[i][j][1];
          ub[(row+8)*USTR + col]   = C[i][j][2];
          ub[(row+8)*USTR + col+1] = C[i][j][3];
        }
    }
    __syncthreads();
    if (wid < 4){
      #pragma unroll
      for (int i = 0; i < 2; i++)
        for (int j = 0; j < nfr; j++){
          int row = wid*32 + i*16 + gid, col = j*8 + tig*2;
          int fr0 = f0 + row, fr1 = f0 + row + 8;
          #pragma unroll
          for (int q = 0; q < 4; q++){
            int cc = col + (q & 1);
            if (cc < ntile){
              int rr = (q < 2) ? row : row + 8;
              float g = C[i][j][q];
              float u = ub[rr*USTR + cc];
              float h = (g / (1.f + __expf(-g))) * u;
              g_H[(size_t)sp[cc]*II + ((q < 2) ? fr0 : fr1)] = h;
            }
          }
        }
    }
  }
}

// ---- kernel 3: down, mma.sync bf16 split ----
// grid (Ee,8). warp w: d-rows d0 + w*16 .. +15.
__global__ void __launch_bounds__(256,2) down_kernel(const float* __restrict__ wd){
  int e = blockIdx.x;
  int nt = g_cnt[e];
  if (nt == 0) return;
  int d0 = blockIdx.y * 128;
  extern __shared__ char dsm[];           // 17408B X hi/lo
  __shared__ int sp[64];
  int tid = threadIdx.x;
  int wid = tid >> 5, lane = tid & 31;
  int gid = lane >> 2, tig = lane & 3;
  const float* wA = wd + ((size_t)(e*Dd) + d0 + wid*16 + gid)*II + tig*2;

  for (int n0 = 0; n0 < nt; n0 += 64){
    int ntile = min(64, nt - n0);
    int nfr = (ntile + 7) >> 3;
    __syncthreads();
    if (tid < 64) sp[tid] = g_slot[e*Tt + ((n0 + tid < nt) ? n0 + tid : n0)];
    __syncthreads();

    float C[8][4];
    #pragma unroll
    for (int j = 0; j < 8; j++)
      #pragma unroll
      for (int q = 0; q < 4; q++) C[j][q] = 0.f;

    for (int k0 = 0; k0 < II; k0 += 64){
      stage_x(dsm, g_H + (size_t)sp[tid>>2]*II + k0 + (tid&3)*16, tid);
      __syncthreads();
      #pragma unroll
      for (int ks = 0; ks < 4; ks++){
        u32 ah[4], al[4];
        load_afrag(wA + k0 + ks*16, II, ah, al);
        char* xb = dsm + gid*XROW + (ks*8 + tig)*4;
        for (int j = 0; j < nfr; j++){
          char* xj = xb + j*8*XROW;
          u32 bh0 = *(u32*)(xj),        bh1 = *(u32*)(xj + 16);
          u32 bl0 = *(u32*)(xj + XHSZ), bl1 = *(u32*)(xj + XHSZ + 16);
          mma16816(C[j], ah, bh0, bh1);
          mma16816(C[j], al, bh0, bh1);
          mma16816(C[j], ah, bl0, bl1);
        }
      }
      __syncthreads();
    }

    int row = d0 + wid*16 + gid;
    for (int j = 0; j < nfr; j++){
      int col = j*8 + tig*2;
      #pragma unroll
      for (int q = 0; q < 4; q++){
        int cc = col + (q & 1);
        if (cc < ntile)
          g_Y[(size_t)sp[cc]*Dd + row + ((q < 2) ? 0 : 8)] = C[j][q];
      }
    }
  }
}

// ---- kernel 4: combine ----
__global__ void combine_kernel(float* __restrict__ out){
  int t = blockIdx.x;
  int i = threadIdx.x;
  float w0 = g_topw[t*4+0], w1 = g_topw[t*4+1];
  float w2 = g_topw[t*4+2], w3 = g_topw[t*4+3];
  const float4* y0 = (const float4*)(g_Y + (size_t)(t*4+0)*Dd);
  const float4* y1 = (const float4*)(g_Y + (size_t)(t*4+1)*Dd);
  const float4* y2 = (const float4*)(g_Y + (size_t)(t*4+2)*Dd);
  const float4* y3 = (const float4*)(g_Y + (size_t)(t*4+3)*Dd);
  float4 a = y0[i], b = y1[i], c = y2[i], d = y3[i];
  float4 r;
  r.x = w0*a.x + w1*b.x + w2*c.x + w3*d.x;
  r.y = w0*a.y + w1*b.y + w2*c.y + w3*d.y;
  r.z = w0*a.z + w1*b.z + w2*c.z + w3*d.z;
  r.w = w0*a.w + w1*b.w + w2*c.w + w3*d.w;
  ((float4*)(out + (size_t)t*Dd))[i] = r;
}

extern "C" void kernel_launch(void* const* d_in, const int* in_sizes, int n_in,
                              void* d_out, int out_size){
  const float* x  = (const float*)d_in[0];
  const float* gw = (const float*)d_in[1];
  const float* wg = (const float*)d_in[2];
  const float* wu = (const float*)d_in[3];
  const float* wd = (const float*)d_in[4];
  float* out = (float*)d_out;
  (void)in_sizes; (void)n_in; (void)out_size;

  zero_kernel<<<1, 64>>>();
  router_kernel<<<Tt, 64>>>(x, gw);
  gateup_kernel<<<dim3(Ee, 4), 256, 128*USTR*4>>>(x, wg, wu);   // 33280 B
  down_kernel<<<dim3(Ee, 8), 256, 2*XHSZ>>>(wd);                // 17408 B
  combine_kernel<<<Tt, 256>>>(out);
}

// round 7
// speedup vs baseline: 1.9929x; 1.9929x over previous
#include <cuda_runtime.h>

#define Tt 512
#define Dd 1024
#define Ee 64
#define II 512
#define KK 4
#define NPAIR (Tt*KK)

typedef unsigned u32;

// ---- scratch ----
__device__ int   g_cnt[Ee];
__device__ int   g_slot[Ee*Tt];
__device__ float g_topw[NPAIR];
__device__ float g_H[NPAIR*II];          // 4 MB
__device__ float g_Y[NPAIR*Dd];          // 8 MB

// smem tile geometry: A 128 rows x 64 k, X 64 rows x 64 k, bf16, 144B row stride
#define AST 144
#define ASZ (128*AST)          // 18432
#define XST 144
#define XSZ (64*XST)           // 9216
#define SMEM_GEMM (2*ASZ + 2*XSZ)  // 55296
#define USTR 65

// fp32 pair -> bf16 hi pair + bf16 residual-lo pair
__device__ __forceinline__ void cvt_hl(float vx, float vy, u32& h, u32& l){
  asm("cvt.rn.bf16x2.f32 %0, %1, %2;" : "=r"(h) : "f"(vy), "f"(vx));
  float r0 = vx - __uint_as_float(h << 16);
  float r1 = vy - __uint_as_float(h & 0xFFFF0000u);
  asm("cvt.rn.bf16x2.f32 %0, %1, %2;" : "=r"(l) : "f"(r1), "f"(r0));
}

__device__ __forceinline__ void mma16816(float* c, const u32* a, u32 b0, u32 b1){
  asm volatile(
    "mma.sync.aligned.m16n8k16.row.col.f32.bf16.bf16.f32 "
    "{%0,%1,%2,%3}, {%4,%5,%6,%7}, {%8,%9}, {%0,%1,%2,%3};"
    : "+f"(c[0]), "+f"(c[1]), "+f"(c[2]), "+f"(c[3])
    : "r"(a[0]), "r"(a[1]), "r"(a[2]), "r"(a[3]), "r"(b0), "r"(b1));
}

__device__ __forceinline__ void ldsm4(u32* r, u32 addr){
  asm volatile("ldmatrix.sync.aligned.m8n8.x4.shared.b16 {%0,%1,%2,%3}, [%4];"
    : "=r"(r[0]), "=r"(r[1]), "=r"(r[2]), "=r"(r[3]) : "r"(addr));
}

__device__ __forceinline__ u32 lds32(u32 addr){
  u32 v; asm volatile("ld.shared.u32 %0, [%1];" : "=r"(v) : "r"(addr)); return v;
}

__device__ __forceinline__ void sts2(u32 addr, u32 a, u32 b){
  asm volatile("st.shared.v2.u32 [%0], {%1,%2};" :: "r"(addr), "r"(a), "r"(b));
}

// stage A chunk from 8 prefetched float4 (rows 0..127, 64 k)
__device__ __forceinline__ void stage_tileA(u32 Ah, u32 Al, const float4* ra, int ar, int akh){
  #pragma unroll
  for (int j = 0; j < 8; j++){
    u32 h0, l0, h1, l1;
    cvt_hl(ra[j].x, ra[j].y, h0, l0);
    cvt_hl(ra[j].z, ra[j].w, h1, l1);
    u32 off = ar*AST + (akh + 4*j)*2;
    sts2(Ah + off, h0, h1);
    sts2(Al + off, l0, l1);
  }
}

// stage X chunk direct from memory (rows 0..63, 64 k)
__device__ __forceinline__ void stage_tileX(u32 Xh, u32 Xl, const float* src, int xn, int xkq){
  #pragma unroll
  for (int j = 0; j < 4; j++){
    float4 v = *(const float4*)(src + 4*j);
    u32 h0, l0, h1, l1;
    cvt_hl(v.x, v.y, h0, l0);
    cvt_hl(v.z, v.w, h1, l1);
    u32 off = xn*XST + (xkq + 4*j)*2;
    sts2(Xh + off, h0, h1);
    sts2(Xl + off, l0, l1);
  }
}

// one 64-k chunk of MMAs: M=128 (8 warps x 16 rows), N=64 (nfr x 8 tokens)
__device__ __forceinline__ void gemm_chunk(float C[8][4], u32 Ah, u32 Al, u32 Xh, u32 Xl,
                                           int wid, int lane, int nfr){
  int gid = lane >> 2, tig = lane & 3;
  u32 abase = (u32)(wid*16 + (lane & 15))*AST + ((lane >> 4) << 4);
  #pragma unroll
  for (int ks = 0; ks < 4; ks++){
    u32 ah[4], al[4];
    ldsm4(ah, Ah + abase + ks*32);
    ldsm4(al, Al + abase + ks*32);
    #pragma unroll
    for (int jb = 0; jb < 8; jb += 4){
      if (jb >= nfr) break;
      u32 bh[4][2], bl[4][2];
      #pragma unroll
      for (int jj = 0; jj < 4; jj++){
        int j = jb + jj;
        if (j < nfr){
          u32 bo = (u32)(j*8 + gid)*XST + ks*32 + tig*4;
          bh[jj][0] = lds32(Xh + bo); bh[jj][1] = lds32(Xh + bo + 16);
          bl[jj][0] = lds32(Xl + bo); bl[jj][1] = lds32(Xl + bo + 16);
        }
      }
      #pragma unroll
      for (int jj = 0; jj < 4; jj++) if (jb+jj < nfr) mma16816(C[jb+jj], ah, bh[jj][0], bh[jj][1]);
      #pragma unroll
      for (int jj = 0; jj < 4; jj++) if (jb+jj < nfr) mma16816(C[jb+jj], al, bh[jj][0], bh[jj][1]);
      #pragma unroll
      for (int jj = 0; jj < 4; jj++) if (jb+jj < nfr) mma16816(C[jb+jj], ah, bl[jj][0], bl[jj][1]);
    }
  }
}

// ---- kernel 0 ----
__global__ void zero_kernel(){
  if (threadIdx.x < Ee) g_cnt[threadIdx.x] = 0;
}

// ---- kernel 1: router ----
__global__ void router_kernel(const float* __restrict__ x, const float* __restrict__ gw){
  int t = blockIdx.x;
  __shared__ float xs[Dd];
  __shared__ float lg[Ee];
  for (int i = threadIdx.x; i < Dd/4; i += 64)
    ((float4*)xs)[i] = ((const float4*)(x + (size_t)t*Dd))[i];
  __syncthreads();
  const float* w = gw + (size_t)threadIdx.x * Dd;
  float acc = 0.f;
  #pragma unroll 4
  for (int d = 0; d < Dd; d += 4){
    float4 wv = *(const float4*)(w + d);
    acc += wv.x*xs[d] + wv.y*xs[d+1] + wv.z*xs[d+2] + wv.w*xs[d+3];
  }
  lg[threadIdx.x] = acc;
  __syncthreads();
  if (threadIdx.x == 0){
    float mx = lg[0];
    for (int i = 1; i < Ee; i++) mx = fmaxf(mx, lg[i]);
    for (int i = 0; i < Ee; i++) lg[i] = __expf(lg[i] - mx);
    float wsum = 0.f; int ids[KK]; float ws[KK];
    for (int k = 0; k < KK; k++){
      int bi = 0; float bv = -1.f;
      for (int i = 0; i < Ee; i++){ float v = lg[i]; if (v > bv){ bv = v; bi = i; } }
      ids[k] = bi; ws[k] = bv; lg[bi] = -2.f; wsum += bv;
    }
    float inv = 1.f / wsum;
    for (int k = 0; k < KK; k++){
      int p = t*KK + k;
      g_topw[p] = ws[k] * inv;
      int slot = atomicAdd(&g_cnt[ids[k]], 1);
      g_slot[ids[k]*Tt + slot] = p;
    }
  }
}

// ---- kernel 2: gate+up GEMM ----
// grid (Ee, 8). A rows: 0-63 = gate f0..f0+63, 64-127 = up f0..f0+63.
// warps 0-3 compute gate, warps 4-7 up; silu fusion via smem exchange.
__global__ void __launch_bounds__(256,2) gateup_kernel(const float* __restrict__ x,
    const float* __restrict__ wg, const float* __restrict__ wu){
  int e = blockIdx.x;
  int nt = g_cnt[e];
  if (nt == 0) return;
  int f0 = blockIdx.y * 64;
  extern __shared__ char dsm[];
  __shared__ int sp[64];
  int tid = threadIdx.x, wid = tid >> 5, lane = tid & 31;
  int gid = lane >> 2, tig = lane & 3;
  u32 sb = (u32)__cvta_generic_to_shared(dsm);
  u32 Ah = sb, Al = sb + ASZ, Xh = sb + 2*ASZ, Xl = sb + 2*ASZ + XSZ;
  float* ub = (float*)dsm;
  int ar = tid >> 1, akh = (tid & 1)*32;
  const float* aBase = (ar < 64 ? wg + ((size_t)e*II + f0 + ar)*Dd
                                : wu + ((size_t)e*II + f0 + ar - 64)*Dd) + akh;
  int xn = tid >> 2, xkq = (tid & 3)*16;

  for (int n0 = 0; n0 < nt; n0 += 64){
    int ntile = min(64, nt - n0), nfr = (ntile + 7) >> 3;
    __syncthreads();
    if (tid < 64) sp[tid] = g_slot[e*Tt + ((n0 + tid < nt) ? n0 + tid : n0)];
    __syncthreads();
    const float* xBase = x + (size_t)(sp[xn] >> 2)*Dd + xkq;
    float4 ra[8];
    #pragma unroll
    for (int j = 0; j < 8; j++) ra[j] = *(const float4*)(aBase + 4*j);
    float C[8][4];
    #pragma unroll
    for (int j = 0; j < 8; j++){ C[j][0]=C[j][1]=C[j][2]=C[j][3]=0.f; }

    for (int c = 0; c < 16; c++){
      __syncthreads();
      stage_tileA(Ah, Al, ra, ar, akh);
      if (c + 1 < 16){
        const float* ap = aBase + (c+1)*64;
        #pragma unroll
        for (int j = 0; j < 8; j++) ra[j] = *(const float4*)(ap + 4*j);
      }
      stage_tileX(Xh, Xl, xBase + c*64, xn, xkq);
      __syncthreads();
      gemm_chunk(C, Ah, Al, Xh, Xl, wid, lane, nfr);
    }

    __syncthreads();
    if (wid >= 4){
      #pragma unroll
      for (int j = 0; j < 8; j++) if (j < nfr)
        #pragma unroll
        for (int q = 0; q < 4; q++){
          int row = (wid-4)*16 + gid + ((q>>1)<<3);
          int col = j*8 + tig*2 + (q&1);
          ub[row*USTR + col] = C[j][q];
        }
    }
    __syncthreads();
    if (wid < 4){
      #pragma unroll
      for (int j = 0; j < 8; j++) if (j < nfr)
        #pragma unroll
        for (int q = 0; q < 4; q++){
          int cc = j*8 + tig*2 + (q&1);
          if (cc < ntile){
            int rl = wid*16 + gid + ((q>>1)<<3);
            float g = C[j][q], u = ub[rl*USTR + cc];
            g_H[(size_t)sp[cc]*II + f0 + rl] = (g / (1.f + __expf(-g))) * u;
          }
        }
    }
  }
}

// ---- kernel 3: down GEMM ----
// grid (Ee, 8): 128 d-rows per block, K=512.
__global__ void __launch_bounds__(256,2) down_kernel(const float* __restrict__ wd){
  int e = blockIdx.x;
  int nt = g_cnt[e];
  if (nt == 0) return;
  int d0 = blockIdx.y * 128;
  extern __shared__ char dsm[];
  __shared__ int sp[64];
  int tid = threadIdx.x, wid = tid >> 5, lane = tid & 31;
  int gid = lane >> 2, tig = lane & 3;
  u32 sb = (u32)__cvta_generic_to_shared(dsm);
  u32 Ah = sb, Al = sb + ASZ, Xh = sb + 2*ASZ, Xl = sb + 2*ASZ + XSZ;
  int ar = tid >> 1, akh = (tid & 1)*32;
  const float* aBase = wd + ((size_t)e*Dd + d0 + ar)*II + akh;
  int xn = tid >> 2, xkq = (tid & 3)*16;

  for (int n0 = 0; n0 < nt; n0 += 64){
    int ntile = min(64, nt - n0), nfr = (ntile + 7) >> 3;
    __syncthreads();
    if (tid < 64) sp[tid] = g_slot[e*Tt + ((n0 + tid < nt) ? n0 + tid : n0)];
    __syncthreads();
    const float* xBase = g_H + (size_t)sp[xn]*II + xkq;
    float4 ra[8];
    #pragma unroll
    for (int j = 0; j < 8; j++) ra[j] = *(const float4*)(aBase + 4*j);
    float C[8][4];
    #pragma unroll
    for (int j = 0; j < 8; j++){ C[j][0]=C[j][1]=C[j][2]=C[j][3]=0.f; }

    for (int c = 0; c < 8; c++){
      __syncthreads();
      stage_tileA(Ah, Al, ra, ar, akh);
      if (c + 1 < 8){
        const float* ap = aBase + (c+1)*64;
        #pragma unroll
        for (int j = 0; j < 8; j++) ra[j] = *(const float4*)(ap + 4*j);
      }
      stage_tileX(Xh, Xl, xBase + c*64, xn, xkq);
      __syncthreads();
      gemm_chunk(C, Ah, Al, Xh, Xl, wid, lane, nfr);
    }

    int drow = d0 + wid*16 + gid;
    #pragma unroll
    for (int j = 0; j < 8; j++) if (j < nfr)
      #pragma unroll
      for (int q = 0; q < 4; q++){
        int cc = j*8 + tig*2 + (q&1);
        if (cc < ntile)
          g_Y[(size_t)sp[cc]*Dd + drow + ((q>>1)<<3)] = C[j][q];
      }
  }
}

// ---- kernel 4: combine ----
__global__ void combine_kernel(float* __restrict__ out){
  int t = blockIdx.x;
  int i = threadIdx.x;
  float w0 = g_topw[t*4+0], w1 = g_topw[t*4+1];
  float w2 = g_topw[t*4+2], w3 = g_topw[t*4+3];
  const float4* y0 = (const float4*)(g_Y + (size_t)(t*4+0)*Dd);
  const float4* y1 = (const float4*)(g_Y + (size_t)(t*4+1)*Dd);
  const float4* y2 = (const float4*)(g_Y + (size_t)(t*4+2)*Dd);
  const float4* y3 = (const float4*)(g_Y + (size_t)(t*4+3)*Dd);
  float4 a = y0[i], b = y1[i], c = y2[i], d = y3[i];
  float4 r;
  r.x = w0*a.x + w1*b.x + w2*c.x + w3*d.x;
  r.y = w0*a.y + w1*b.y + w2*c.y + w3*d.y;
  r.z = w0*a.z + w1*b.z + w2*c.z + w3*d.z;
  r.w = w0*a.w + w1*b.w + w2*c.w + w3*d.w;
  ((float4*)(out + (size_t)t*Dd))[i] = r;
}

extern "C" void kernel_launch(void* const* d_in, const int* in_sizes, int n_in,
                              void* d_out, int out_size){
  const float* x  = (const float*)d_in[0];
  const float* gw = (const float*)d_in[1];
  const float* wg = (const float*)d_in[2];
  const float* wu = (const float*)d_in[3];
  const float* wd = (const float*)d_in[4];
  float* out = (float*)d_out;
  (void)in_sizes; (void)n_in; (void)out_size;

  static int inited = 0;
  if (!inited){
    cudaFuncSetAttribute(gateup_kernel, cudaFuncAttributeMaxDynamicSharedMemorySize, SMEM_GEMM);
    cudaFuncSetAttribute(down_kernel,   cudaFuncAttributeMaxDynamicSharedMemorySize, SMEM_GEMM);
    inited = 1;
  }

  zero_kernel<<<1, 64>>>();
  router_kernel<<<Tt, 64>>>(x, gw);
  gateup_kernel<<<dim3(Ee, 8), 256, SMEM_GEMM>>>(x, wg, wu);
  down_kernel<<<dim3(Ee, 8), 256, SMEM_GEMM>>>(wd);
  combine_kernel<<<Tt, 256>>>(out);
}

// round 8
// speedup vs baseline: 2.1920x; 1.0999x over previous
#include <cuda_runtime.h>

#define Tt 512
#define Dd 1024
#define Ee 64
#define II 512
#define KK 4
#define NPAIR (Tt*KK)

typedef unsigned u32;

// ---- scratch ----
__device__ int   g_cnt[Ee];
__device__ int   g_slot[Ee*Tt];
__device__ float g_topw[NPAIR];
__device__ float g_H[NPAIR*II];          // 4 MB
__device__ float g_Y[NPAIR*Dd];          // 8 MB

// smem tile geometry: A 128 rows x 64 k, X 64 rows x 64 k, bf16, 144B row stride
#define AST 144
#define ASZ (128*AST)          // 18432
#define XST 144
#define XSZ (64*XST)           // 9216
#define SMEM_GEMM (2*ASZ + 2*XSZ)  // 55296
#define USTR 65

// fp32 pair -> bf16 hi pair + bf16 residual-lo pair
__device__ __forceinline__ void cvt_hl(float vx, float vy, u32& h, u32& l){
  asm("cvt.rn.bf16x2.f32 %0, %1, %2;" : "=r"(h) : "f"(vy), "f"(vx));
  float r0 = vx - __uint_as_float(h << 16);
  float r1 = vy - __uint_as_float(h & 0xFFFF0000u);
  asm("cvt.rn.bf16x2.f32 %0, %1, %2;" : "=r"(l) : "f"(r1), "f"(r0));
}

__device__ __forceinline__ void mma16816(float* c, const u32* a, u32 b0, u32 b1){
  asm volatile(
    "mma.sync.aligned.m16n8k16.row.col.f32.bf16.bf16.f32 "
    "{%0,%1,%2,%3}, {%4,%5,%6,%7}, {%8,%9}, {%0,%1,%2,%3};"
    : "+f"(c[0]), "+f"(c[1]), "+f"(c[2]), "+f"(c[3])
    : "r"(a[0]), "r"(a[1]), "r"(a[2]), "r"(a[3]), "r"(b0), "r"(b1));
}

__device__ __forceinline__ void ldsm4(u32* r, u32 addr){
  asm volatile("ldmatrix.sync.aligned.m8n8.x4.shared.b16 {%0,%1,%2,%3}, [%4];"
    : "=r"(r[0]), "=r"(r[1]), "=r"(r[2]), "=r"(r[3]) : "r"(addr));
}

__device__ __forceinline__ void sts2(u32 addr, u32 a, u32 b){
  asm volatile("st.shared.v2.u32 [%0], {%1,%2};" :: "r"(addr), "r"(a), "r"(b));
}

// stage A chunk from 8 prefetched float4 (rows 0..127, 64 k)
__device__ __forceinline__ void stage_tileA(u32 Ah, u32 Al, const float4* ra, int ar, int akh){
  #pragma unroll
  for (int j = 0; j < 8; j++){
    u32 h0, l0, h1, l1;
    cvt_hl(ra[j].x, ra[j].y, h0, l0);
    cvt_hl(ra[j].z, ra[j].w, h1, l1);
    u32 off = ar*AST + (akh + 4*j)*2;
    sts2(Ah + off, h0, h1);
    sts2(Al + off, l0, l1);
  }
}

// stage X chunk from 4 prefetched float4 (rows 0..63, 64 k)
__device__ __forceinline__ void stage_tileX(u32 Xh, u32 Xl, const float4* rx, int xn, int xkq){
  #pragma unroll
  for (int j = 0; j < 4; j++){
    u32 h0, l0, h1, l1;
    cvt_hl(rx[j].x, rx[j].y, h0, l0);
    cvt_hl(rx[j].z, rx[j].w, h1, l1);
    u32 off = xn*XST + (xkq + 4*j)*2;
    sts2(Xh + off, h0, h1);
    sts2(Xl + off, l0, l1);
  }
}

// one 64-k chunk of MMAs: M=128 (8 warps x 16 rows), N = jpairs x 16 tokens
__device__ __forceinline__ void gemm_chunk(float C[8][4], u32 Ah, u32 Al, u32 Xh, u32 Xl,
                                           int wid, int lane, int jpairs){
  u32 abase = (u32)(wid*16 + (lane & 15))*AST + ((lane >> 4) << 4);
  int q = lane >> 3, rr = lane & 7;
  u32 bbase = (u32)(((q >> 1) << 3) + rr)*XST + (q & 1)*16;
  #pragma unroll
  for (int ks = 0; ks < 4; ks++){
    u32 ah[4], al[4];
    ldsm4(ah, Ah + abase + ks*32);
    ldsm4(al, Al + abase + ks*32);
    #pragma unroll
    for (int jp = 0; jp < 4; jp++){
      if (jp >= jpairs) break;
      u32 bh[4], bl[4];
      ldsm4(bh, Xh + bbase + (u32)(jp*16)*XST + ks*32);
      ldsm4(bl, Xl + bbase + (u32)(jp*16)*XST + ks*32);
      int j0 = jp*2, j1 = jp*2 + 1;
      mma16816(C[j0], ah, bh[0], bh[1]);
      mma16816(C[j1], ah, bh[2], bh[3]);
      mma16816(C[j0], al, bh[0], bh[1]);
      mma16816(C[j1], al, bh[2], bh[3]);
      mma16816(C[j0], ah, bl[0], bl[1]);
      mma16816(C[j1], ah, bl[2], bl[3]);
    }
  }
}

// ---- kernel 0 ----
__global__ void zero_kernel(){
  if (threadIdx.x < Ee) g_cnt[threadIdx.x] = 0;
}

// ---- kernel 1: router ----
__global__ void router_kernel(const float* __restrict__ x, const float* __restrict__ gw){
  int t = blockIdx.x;
  __shared__ float xs[Dd];
  __shared__ float lg[Ee];
  for (int i = threadIdx.x; i < Dd/4; i += 64)
    ((float4*)xs)[i] = ((const float4*)(x + (size_t)t*Dd))[i];
  __syncthreads();
  const float* w = gw + (size_t)threadIdx.x * Dd;
  float acc = 0.f;
  #pragma unroll 4
  for (int d = 0; d < Dd; d += 4){
    float4 wv = *(const float4*)(w + d);
    acc += wv.x*xs[d] + wv.y*xs[d+1] + wv.z*xs[d+2] + wv.w*xs[d+3];
  }
  lg[threadIdx.x] = acc;
  __syncthreads();
  if (threadIdx.x == 0){
    float mx = lg[0];
    for (int i = 1; i < Ee; i++) mx = fmaxf(mx, lg[i]);
    for (int i = 0; i < Ee; i++) lg[i] = __expf(lg[i] - mx);
    float wsum = 0.f; int ids[KK]; float ws[KK];
    for (int k = 0; k < KK; k++){
      int bi = 0; float bv = -1.f;
      for (int i = 0; i < Ee; i++){ float v = lg[i]; if (v > bv){ bv = v; bi = i; } }
      ids[k] = bi; ws[k] = bv; lg[bi] = -2.f; wsum += bv;
    }
    float inv = 1.f / wsum;
    for (int k = 0; k < KK; k++){
      int p = t*KK + k;
      g_topw[p] = ws[k] * inv;
      int slot = atomicAdd(&g_cnt[ids[k]], 1);
      g_slot[ids[k]*Tt + slot] = p;
    }
  }
}

// ---- kernel 2: gate+up GEMM ----
// grid (Ee, 8). A rows: 0-63 = gate f0..f0+63, 64-127 = up f0..f0+63.
// warps 0-3 compute gate, warps 4-7 up; silu fusion via smem exchange.
__global__ void __launch_bounds__(256,2) gateup_kernel(const float* __restrict__ x,
    const float* __restrict__ wg, const float* __restrict__ wu){
  int e = blockIdx.x;
  int nt = g_cnt[e];
  if (nt == 0) return;
  int f0 = blockIdx.y * 64;
  extern __shared__ char dsm[];
  __shared__ int sp[64];
  int tid = threadIdx.x, wid = tid >> 5, lane = tid & 31;
  int gid = lane >> 2, tig = lane & 3;
  u32 sb = (u32)__cvta_generic_to_shared(dsm);
  u32 Ah = sb, Al = sb + ASZ, Xh = sb + 2*ASZ, Xl = sb + 2*ASZ + XSZ;
  float* ub = (float*)dsm;
  int ar = tid >> 1, akh = (tid & 1)*32;
  const float* aBase = (ar < 64 ? wg + ((size_t)e*II + f0 + ar)*Dd
                                : wu + ((size_t)e*II + f0 + ar - 64)*Dd) + akh;
  int xn = tid >> 2, xkq = (tid & 3)*16;

  for (int n0 = 0; n0 < nt; n0 += 64){
    int ntile = min(64, nt - n0), nfr = (ntile + 7) >> 3;
    int jpairs = (nfr + 1) >> 1;
    __syncthreads();
    if (tid < 64) sp[tid] = g_slot[e*Tt + ((n0 + tid < nt) ? n0 + tid : n0)];
    __syncthreads();
    const float* xBase = x + (size_t)(sp[xn] >> 2)*Dd + xkq;
    float4 ra[8], rx[4];
    #pragma unroll
    for (int j = 0; j < 8; j++) ra[j] = *(const float4*)(aBase + 4*j);
    #pragma unroll
    for (int j = 0; j < 4; j++) rx[j] = *(const float4*)(xBase + 4*j);
    float C[8][4];
    #pragma unroll
    for (int j = 0; j < 8; j++){ C[j][0]=C[j][1]=C[j][2]=C[j][3]=0.f; }

    for (int c = 0; c < 16; c++){
      __syncthreads();
      stage_tileA(Ah, Al, ra, ar, akh);
      stage_tileX(Xh, Xl, rx, xn, xkq);
      if (c + 1 < 16){
        const float* ap = aBase + (c+1)*64;
        #pragma unroll
        for (int j = 0; j < 8; j++) ra[j] = *(const float4*)(ap + 4*j);
        const float* xp = xBase + (c+1)*64;
        #pragma unroll
        for (int j = 0; j < 4; j++) rx[j] = *(const float4*)(xp + 4*j);
      }
      __syncthreads();
      gemm_chunk(C, Ah, Al, Xh, Xl, wid, lane, jpairs);
    }

    __syncthreads();
    if (wid >= 4){
      #pragma unroll
      for (int j = 0; j < 8; j++) if (j < nfr)
        #pragma unroll
        for (int q = 0; q < 4; q++){
          int row = (wid-4)*16 + gid + ((q>>1)<<3);
          int col = j*8 + tig*2 + (q&1);
          ub[row*USTR + col] = C[j][q];
        }
    }
    __syncthreads();
    if (wid < 4){
      #pragma unroll
      for (int j = 0; j < 8; j++) if (j < nfr)
        #pragma unroll
        for (int q = 0; q < 4; q++){
          int cc = j*8 + tig*2 + (q&1);
          if (cc < ntile){
            int rl = wid*16 + gid + ((q>>1)<<3);
            float g = C[j][q], u = ub[rl*USTR + cc];
            g_H[(size_t)sp[cc]*II + f0 + rl] = (g / (1.f + __expf(-g))) * u;
          }
        }
    }
  }
}

// ---- kernel 3: down GEMM ----
// grid (Ee, 8): 128 d-rows per block, K=512.
__global__ void __launch_bounds__(256,2) down_kernel(const float* __restrict__ wd){
  int e = blockIdx.x;
  int nt = g_cnt[e];
  if (nt == 0) return;
  int d0 = blockIdx.y * 128;
  extern __shared__ char dsm[];
  __shared__ int sp[64];
  int tid = threadIdx.x, wid = tid >> 5, lane = tid & 31;
  int gid = lane >> 2, tig = lane & 3;
  u32 sb = (u32)__cvta_generic_to_shared(dsm);
  u32 Ah = sb, Al = sb + ASZ, Xh = sb + 2*ASZ, Xl = sb + 2*ASZ + XSZ;
  int ar = tid >> 1, akh = (tid & 1)*32;
  const float* aBase = wd + ((size_t)e*Dd + d0 + ar)*II + akh;
  int xn = tid >> 2, xkq = (tid & 3)*16;

  for (int n0 = 0; n0 < nt; n0 += 64){
    int ntile = min(64, nt - n0), nfr = (ntile + 7) >> 3;
    int jpairs = (nfr + 1) >> 1;
    __syncthreads();
    if (tid < 64) sp[tid] = g_slot[e*Tt + ((n0 + tid < nt) ? n0 + tid : n0)];
    __syncthreads();
    const float* xBase = g_H + (size_t)sp[xn]*II + xkq;
    float4 ra[8], rx[4];
    #pragma unroll
    for (int j = 0; j < 8; j++) ra[j] = *(const float4*)(aBase + 4*j);
    #pragma unroll
    for (int j = 0; j < 4; j++) rx[j] = *(const float4*)(xBase + 4*j);
    float C[8][4];
    #pragma unroll
    for (int j = 0; j < 8; j++){ C[j][0]=C[j][1]=C[j][2]=C[j][3]=0.f; }

    for (int c = 0; c < 8; c++){
      __syncthreads();
      stage_tileA(Ah, Al, ra, ar, akh);
      stage_tileX(Xh, Xl, rx, xn, xkq);
      if (c + 1 < 8){
        const float* ap = aBase + (c+1)*64;
        #pragma unroll
        for (int j = 0; j < 8; j++) ra[j] = *(const float4*)(ap + 4*j);
        const float* xp = xBase + (c+1)*64;
        #pragma unroll
        for (int j = 0; j < 4; j++) rx[j] = *(const float4*)(xp + 4*j);
      }
      __syncthreads();
      gemm_chunk(C, Ah, Al, Xh, Xl, wid, lane, jpairs);
    }

    int drow = d0 + wid*16 + gid;
    #pragma unroll
    for (int j = 0; j < 8; j++) if (j < nfr)
      #pragma unroll
      for (int q = 0; q < 4; q++){
        int cc = j*8 + tig*2 + (q&1);
        if (cc < ntile)
          g_Y[(size_t)sp[cc]*Dd + drow + ((q>>1)<<3)] = C[j][q];
      }
  }
}

// ---- kernel 4: combine ----
__global__ void combine_kernel(float* __restrict__ out){
  int t = blockIdx.x;
  int i = threadIdx.x;
  float w0 = g_topw[t*4+0], w1 = g_topw[t*4+1];
  float w2 = g_topw[t*4+2], w3 = g_topw[t*4+3];
  const float4* y0 = (const float4*)(g_Y + (size_t)(t*4+0)*Dd);
  const float4* y1 = (const float4*)(g_Y + (size_t)(t*4+1)*Dd);
  const float4* y2 = (const float4*)(g_Y + (size_t)(t*4+2)*Dd);
  const float4* y3 = (const float4*)(g_Y + (size_t)(t*4+3)*Dd);
  float4 a = y0[i], b = y1[i], c = y2[i], d = y3[i];
  float4 r;
  r.x = w0*a.x + w1*b.x + w2*c.x + w3*d.x;
  r.y = w0*a.y + w1*b.y + w2*c.y + w3*d.y;
  r.z = w0*a.z + w1*b.z + w2*c.z + w3*d.z;
  r.w = w0*a.w + w1*b.w + w2*c.w + w3*d.w;
  ((float4*)(out + (size_t)t*Dd))[i] = r;
}

extern "C" void kernel_launch(void* const* d_in, const int* in_sizes, int n_in,
                              void* d_out, int out_size){
  const float* x  = (const float*)d_in[0];
  const float* gw = (const float*)d_in[1];
  const float* wg = (const float*)d_in[2];
  const float* wu = (const float*)d_in[3];
  const float* wd = (const float*)d_in[4];
  float* out = (float*)d_out;
  (void)in_sizes; (void)n_in; (void)out_size;

  static int inited = 0;
  if (!inited){
    cudaFuncSetAttribute(gateup_kernel, cudaFuncAttributeMaxDynamicSharedMemorySize, SMEM_GEMM);
    cudaFuncSetAttribute(down_kernel,   cudaFuncAttributeMaxDynamicSharedMemorySize, SMEM_GEMM);
    inited = 1;
  }

  zero_kernel<<<1, 64>>>();
  router_kernel<<<Tt, 64>>>(x, gw);
  gateup_kernel<<<dim3(Ee, 8), 256, SMEM_GEMM>>>(x, wg, wu);
  down_kernel<<<dim3(Ee, 8), 256, SMEM_GEMM>>>(wd);
  combine_kernel<<<Tt, 256>>>(out);
}

// round 9
// speedup vs baseline: 2.6695x; 1.2179x over previous
#include <cuda_runtime.h>

#define Tt 512
#define Dd 1024
#define Ee 64
#define II 512
#define KK 4
#define NPAIR (Tt*KK)

typedef unsigned u32;
typedef unsigned short u16;

// ---- scratch ----
__device__ int   g_cnt[Ee];
__device__ int   g_slot[Ee*Tt];
__device__ float g_topw[NPAIR];
__device__ u16   g_xh[Tt*Dd];            // x as bf16 hi
__device__ u16   g_xl[Tt*Dd];            // x residual lo
__device__ u16   g_Hh[NPAIR*II];         // H bf16 hi
__device__ u16   g_Hl[NPAIR*II];         // H residual lo
__device__ float g_Y[NPAIR*Dd];          // 8 MB

// ---- pipeline geometry ----
#define KC 32                 // k per chunk
#define STG 3
#define AST4 144              // A row stride bytes (fp32, 32 floats + pad)
#define ASZ4 (128*AST4)       // 18432
#define XSTB 80               // X row stride bytes (bf16, 64B data + pad)
#define XSZB (64*XSTB)        // 5120
#define STAGE_SZ (ASZ4 + 2*XSZB)   // 28672
#define SMEM_TOT (STG*STAGE_SZ)    // 86016
#define USTR 65

__device__ __forceinline__ void cvt_hl(float vx, float vy, u32& h, u32& l){
  asm("cvt.rn.bf16x2.f32 %0, %1, %2;" : "=r"(h) : "f"(vy), "f"(vx));
  float r0 = vx - __uint_as_float(h << 16);
  float r1 = vy - __uint_as_float(h & 0xFFFF0000u);
  asm("cvt.rn.bf16x2.f32 %0, %1, %2;" : "=r"(l) : "f"(r1), "f"(r0));
}

__device__ __forceinline__ void mma16816(float* c, const u32* a, u32 b0, u32 b1){
  asm volatile(
    "mma.sync.aligned.m16n8k16.row.col.f32.bf16.bf16.f32 "
    "{%0,%1,%2,%3}, {%4,%5,%6,%7}, {%8,%9}, {%0,%1,%2,%3};"
    : "+f"(c[0]), "+f"(c[1]), "+f"(c[2]), "+f"(c[3])
    : "r"(a[0]), "r"(a[1]), "r"(a[2]), "r"(a[3]), "r"(b0), "r"(b1));
}

__device__ __forceinline__ void ldsm4(u32* r, u32 addr){
  asm volatile("ldmatrix.sync.aligned.m8n8.x4.shared.b16 {%0,%1,%2,%3}, [%4];"
    : "=r"(r[0]), "=r"(r[1]), "=r"(r[2]), "=r"(r[3]) : "r"(addr));
}

__device__ __forceinline__ float2 lds64f(u32 a){
  float2 v; asm volatile("ld.shared.v2.f32 {%0,%1}, [%2];" : "=f"(v.x), "=f"(v.y) : "r"(a));
  return v;
}

__device__ __forceinline__ void cpa16(u32 dst, const void* src){
  asm volatile("cp.async.cg.shared.global [%0], [%1], 16;" :: "r"(dst), "l"(src));
}
#define CPA_COMMIT asm volatile("cp.async.commit_group;" ::: "memory")
#define CPA_WAIT1  asm volatile("cp.async.wait_group 1;" ::: "memory")

// build A fragment pair (hi/lo) from fp32 smem tile
__device__ __forceinline__ void afrag(u32 Ast, int wid, int lane, int ks, u32* ah, u32* al){
  int gid = lane >> 2, tig = lane & 3;
  u32 a0 = Ast + (u32)(wid*16 + gid)*AST4 + (u32)(ks*16 + tig*2)*4;
  float2 v00 = lds64f(a0);
  float2 v10 = lds64f(a0 + 8*AST4);
  float2 v01 = lds64f(a0 + 32);
  float2 v11 = lds64f(a0 + 8*AST4 + 32);
  cvt_hl(v00.x, v00.y, ah[0], al[0]);
  cvt_hl(v10.x, v10.y, ah[1], al[1]);
  cvt_hl(v01.x, v01.y, ah[2], al[2]);
  cvt_hl(v11.x, v11.y, ah[3], al[3]);
}

// consume one staged chunk: 2 k16 steps, jpairs n-pairs
__device__ __forceinline__ void consume(float C[8][4], u32 stg, int wid, int lane, int jpairs){
  u32 Ast = stg, Xh = stg + ASZ4, Xl = Xh + XSZB;
  int q = lane >> 3, rr = lane & 7;
  u32 bbase = (u32)(((q >> 1) << 3) + rr)*XSTB + (q & 1)*16;
  #pragma unroll
  for (int ks = 0; ks < 2; ks++){
    u32 ah[4], al[4];
    afrag(Ast, wid, lane, ks, ah, al);
    #pragma unroll
    for (int jp = 0; jp < 4; jp++){
      if (jp >= jpairs) break;
      u32 bh[4], bl[4];
      ldsm4(bh, Xh + bbase + (u32)(jp*16)*XSTB + ks*32);
      ldsm4(bl, Xl + bbase + (u32)(jp*16)*XSTB + ks*32);
      int j0 = jp*2, j1 = jp*2 + 1;
      mma16816(C[j0], ah, bh[0], bh[1]);
      mma16816(C[j1], ah, bh[2], bh[3]);
      mma16816(C[j0], al, bh[0], bh[1]);
      mma16816(C[j1], al, bh[2], bh[3]);
      mma16816(C[j0], ah, bl[0], bl[1]);
      mma16816(C[j1], ah, bl[2], bl[3]);
    }
  }
}

// ---- kernel 0 ----
__global__ void zero_kernel(){
  if (threadIdx.x < Ee) g_cnt[threadIdx.x] = 0;
}

// ---- kernel 0b: x -> bf16 hi/lo ----
__global__ void cvtx_kernel(const float* __restrict__ x){
  int i = blockIdx.x*256 + threadIdx.x;       // one float4 per thread
  float4 v = ((const float4*)x)[i];
  u32 h0, l0, h1, l1;
  cvt_hl(v.x, v.y, h0, l0);
  cvt_hl(v.z, v.w, h1, l1);
  ((uint2*)g_xh)[i] = make_uint2(h0, h1);
  ((uint2*)g_xl)[i] = make_uint2(l0, l1);
}

// ---- kernel 1: router ----
__global__ void router_kernel(const float* __restrict__ x, const float* __restrict__ gw){
  int t = blockIdx.x;
  __shared__ float xs[Dd];
  __shared__ float lg[Ee];
  for (int i = threadIdx.x; i < Dd/4; i += 64)
    ((float4*)xs)[i] = ((const float4*)(x + (size_t)t*Dd))[i];
  __syncthreads();
  const float* w = gw + (size_t)threadIdx.x * Dd;
  float acc = 0.f;
  #pragma unroll 4
  for (int d = 0; d < Dd; d += 4){
    float4 wv = *(const float4*)(w + d);
    acc += wv.x*xs[d] + wv.y*xs[d+1] + wv.z*xs[d+2] + wv.w*xs[d+3];
  }
  lg[threadIdx.x] = acc;
  __syncthreads();
  if (threadIdx.x == 0){
    float mx = lg[0];
    for (int i = 1; i < Ee; i++) mx = fmaxf(mx, lg[i]);
    for (int i = 0; i < Ee; i++) lg[i] = __expf(lg[i] - mx);
    float wsum = 0.f; int ids[KK]; float ws[KK];
    for (int k = 0; k < KK; k++){
      int bi = 0; float bv = -1.f;
      for (int i = 0; i < Ee; i++){ float v = lg[i]; if (v > bv){ bv = v; bi = i; } }
      ids[k] = bi; ws[k] = bv; lg[bi] = -2.f; wsum += bv;
    }
    float inv = 1.f / wsum;
    for (int k = 0; k < KK; k++){
      int p = t*KK + k;
      g_topw[p] = ws[k] * inv;
      int slot = atomicAdd(&g_cnt[ids[k]], 1);
      g_slot[ids[k]*Tt + slot] = p;
    }
  }
}

// ---- kernel 2: gate+up GEMM (cp.async pipeline) ----
// grid (Ee, 8). A rows 0-63 = gate f0.., 64-127 = up f0..; warps 0-3 gate, 4-7 up.
__global__ void __launch_bounds__(256,2) gateup_kernel(
    const float* __restrict__ wg, const float* __restrict__ wu){
  int e = blockIdx.x;
  int nt = g_cnt[e];
  if (nt == 0) return;
  int f0 = blockIdx.y * 64;
  extern __shared__ char dsm[];
  __shared__ int sp[64];
  int tid = threadIdx.x, wid = tid >> 5, lane = tid & 31;
  int gid = lane >> 2, tig = lane & 3;
  u32 sb = (u32)__cvta_generic_to_shared(dsm);
  float* ub = (float*)dsm;

  int arow = tid >> 1;
  u32 adst = (u32)arow*AST4 + (u32)(tid & 1)*64;
  const float* aPtr = (arow < 64 ? wg + ((size_t)e*II + f0 + arow)*Dd
                                 : wu + ((size_t)e*II + f0 + arow - 64)*Dd) + (tid & 1)*16;
  int xrow = tid >> 2, xseg = tid & 3;
  u32 xdst = (u32)xrow*XSTB + (u32)xseg*16;

  for (int n0 = 0; n0 < nt; n0 += 64){
    int ntile = min(64, nt - n0), nfr = (ntile + 7) >> 3;
    int jpairs = (nfr + 1) >> 1;
    __syncthreads();
    if (tid < 64) sp[tid] = g_slot[e*Tt + ((n0 + tid < nt) ? n0 + tid : n0)];
    __syncthreads();
    const u16* xhPtr = g_xh + (size_t)(sp[xrow] >> 2)*Dd + xseg*8;
    const u16* xlPtr = g_xl + (size_t)(sp[xrow] >> 2)*Dd + xseg*8;

    float C[8][4];
    #pragma unroll
    for (int j = 0; j < 8; j++){ C[j][0]=C[j][1]=C[j][2]=C[j][3]=0.f; }

    #pragma unroll
    for (int s = 0; s < STG-1; s++){
      u32 st = sb + s*STAGE_SZ;
      #pragma unroll
      for (int j = 0; j < 4; j++) cpa16(st + adst + j*16, aPtr + s*KC + j*4);
      cpa16(st + ASZ4 + xdst,        xhPtr + s*KC);
      cpa16(st + ASZ4 + XSZB + xdst, xlPtr + s*KC);
      CPA_COMMIT;
    }
    for (int c = 0; c < Dd/KC; c++){
      CPA_WAIT1;
      __syncthreads();
      int cn = c + STG - 1;
      if (cn < Dd/KC){
        u32 st = sb + (cn % STG)*STAGE_SZ;
        #pragma unroll
        for (int j = 0; j < 4; j++) cpa16(st + adst + j*16, aPtr + cn*KC + j*4);
        cpa16(st + ASZ4 + xdst,        xhPtr + cn*KC);
        cpa16(st + ASZ4 + XSZB + xdst, xlPtr + cn*KC);
      }
      CPA_COMMIT;
      consume(C, sb + (c % STG)*STAGE_SZ, wid, lane, jpairs);
    }

    __syncthreads();
    if (wid >= 4){
      #pragma unroll
      for (int j = 0; j < 8; j++) if (j < nfr)
        #pragma unroll
        for (int q = 0; q < 4; q++){
          int row = (wid-4)*16 + gid + ((q>>1)<<3);
          int col = j*8 + tig*2 + (q&1);
          ub[row*USTR + col] = C[j][q];
        }
    }
    __syncthreads();
    if (wid < 4){
      #pragma unroll
      for (int j = 0; j < 8; j++) if (j < nfr)
        #pragma unroll
        for (int q = 0; q < 4; q++){
          int cc = j*8 + tig*2 + (q&1);
          if (cc < ntile){
            int rl = wid*16 + gid + ((q>>1)<<3);
            float g = C[j][q], u = ub[rl*USTR + cc];
            float h = (g / (1.f + __expf(-g))) * u;
            u16 hs; asm("cvt.rn.bf16.f32 %0, %1;" : "=h"(hs) : "f"(h));
            float lo = h - __uint_as_float(((u32)hs) << 16);
            u16 ls; asm("cvt.rn.bf16.f32 %0, %1;" : "=h"(ls) : "f"(lo));
            size_t idx = (size_t)sp[cc]*II + f0 + rl;
            g_Hh[idx] = hs;
            g_Hl[idx] = ls;
          }
        }
    }
    __syncthreads();   // ub reuse vs next n0 staging
  }
}

// ---- kernel 3: down GEMM (cp.async pipeline) ----
// grid (Ee, 8): 128 d-rows per block, K=512.
__global__ void __launch_bounds__(256,2) down_kernel(const float* __restrict__ wd){
  int e = blockIdx.x;
  int nt = g_cnt[e];
  if (nt == 0) return;
  int d0 = blockIdx.y * 128;
  extern __shared__ char dsm[];
  __shared__ int sp[64];
  int tid = threadIdx.x, wid = tid >> 5, lane = tid & 31;
  int gid = lane >> 2, tig = lane & 3;
  u32 sb = (u32)__cvta_generic_to_shared(dsm);

  int arow = tid >> 1;
  u32 adst = (u32)arow*AST4 + (u32)(tid & 1)*64;
  const float* aPtr = wd + ((size_t)e*Dd + d0 + arow)*II + (tid & 1)*16;
  int xrow = tid >> 2, xseg = tid & 3;
  u32 xdst = (u32)xrow*XSTB + (u32)xseg*16;

  for (int n0 = 0; n0 < nt; n0 += 64){
    int ntile = min(64, nt - n0), nfr = (ntile + 7) >> 3;
    int jpairs = (nfr + 1) >> 1;
    __syncthreads();
    if (tid < 64) sp[tid] = g_slot[e*Tt + ((n0 + tid < nt) ? n0 + tid : n0)];
    __syncthreads();
    const u16* xhPtr = g_Hh + (size_t)sp[xrow]*II + xseg*8;
    const u16* xlPtr = g_Hl + (size_t)sp[xrow]*II + xseg*8;

    float C[8][4];
    #pragma unroll
    for (int j = 0; j < 8; j++){ C[j][0]=C[j][1]=C[j][2]=C[j][3]=0.f; }

    #pragma unroll
    for (int s = 0; s < STG-1; s++){
      u32 st = sb + s*STAGE_SZ;
      #pragma unroll
      for (int j = 0; j < 4; j++) cpa16(st + adst + j*16, aPtr + s*KC + j*4);
      cpa16(st + ASZ4 + xdst,        xhPtr + s*KC);
      cpa16(st + ASZ4 + XSZB + xdst, xlPtr + s*KC);
      CPA_COMMIT;
    }
    for (int c = 0; c < II/KC; c++){
      CPA_WAIT1;
      __syncthreads();
      int cn = c + STG - 1;
      if (cn < II/KC){
        u32 st = sb + (cn % STG)*STAGE_SZ;
        #pragma unroll
        for (int j = 0; j < 4; j++) cpa16(st + adst + j*16, aPtr + cn*KC + j*4);
        cpa16(st + ASZ4 + xdst,        xhPtr + cn*KC);
        cpa16(st + ASZ4 + XSZB + xdst, xlPtr + cn*KC);
      }
      CPA_COMMIT;
      consume(C, sb + (c % STG)*STAGE_SZ, wid, lane, jpairs);
    }

    int drow = d0 + wid*16 + gid;
    #pragma unroll
    for (int j = 0; j < 8; j++) if (j < nfr)
      #pragma unroll
      for (int q = 0; q < 4; q++){
        int cc = j*8 + tig*2 + (q&1);
        if (cc < ntile)
          g_Y[(size_t)sp[cc]*Dd + drow + ((q>>1)<<3)] = C[j][q];
      }
  }
}

// ---- kernel 4: combine ----
__global__ void combine_kernel(float* __restrict__ out){
  int t = blockIdx.x;
  int i = threadIdx.x;
  float w0 = g_topw[t*4+0], w1 = g_topw[t*4+1];
  float w2 = g_topw[t*4+2], w3 = g_topw[t*4+3];
  const float4* y0 = (const float4*)(g_Y + (size_t)(t*4+0)*Dd);
  const float4* y1 = (const float4*)(g_Y + (size_t)(t*4+1)*Dd);
  const float4* y2 = (const float4*)(g_Y + (size_t)(t*4+2)*Dd);
  const float4* y3 = (const float4*)(g_Y + (size_t)(t*4+3)*Dd);
  float4 a = y0[i], b = y1[i], c = y2[i], d = y3[i];
  float4 r;
  r.x = w0*a.x + w1*b.x + w2*c.x + w3*d.x;
  r.y = w0*a.y + w1*b.y + w2*c.y + w3*d.y;
  r.z = w0*a.z + w1*b.z + w2*c.z + w3*d.z;
  r.w = w0*a.w + w1*b.w + w2*c.w + w3*d.w;
  ((float4*)(out + (size_t)t*Dd))[i] = r;
}

extern "C" void kernel_launch(void* const* d_in, const int* in_sizes, int n_in,
                              void* d_out, int out_size){
  const float* x  = (const float*)d_in[0];
  const float* gw = (const float*)d_in[1];
  const float* wg = (const float*)d_in[2];
  const float* wu = (const float*)d_in[3];
  const float* wd = (const float*)d_in[4];
  float* out = (float*)d_out;
  (void)in_sizes; (void)n_in; (void)out_size;

  static int inited = 0;
  if (!inited){
    cudaFuncSetAttribute(gateup_kernel, cudaFuncAttributeMaxDynamicSharedMemorySize, SMEM_TOT);
    cudaFuncSetAttribute(down_kernel,   cudaFuncAttributeMaxDynamicSharedMemorySize, SMEM_TOT);
    inited = 1;
  }

  zero_kernel<<<1, 64>>>();
  cvtx_kernel<<<Tt, 256>>>(x);
  router_kernel<<<Tt, 64>>>(x, gw);
  gateup_kernel<<<dim3(Ee, 8), 256, SMEM_TOT>>>(wg, wu);
  down_kernel<<<dim3(Ee, 8), 256, SMEM_TOT>>>(wd);
  combine_kernel<<<Tt, 256>>>(out);
}

// round 11
// speedup vs baseline: 2.9833x; 1.1175x over previous
#include <cuda_runtime.h>

#define Tt 512
#define Dd 1024
#define Ee 64
#define II 512
#define KK 4
#define NPAIR (Tt*KK)

typedef unsigned u32;
typedef unsigned short u16;

// ---- scratch ----
__device__ int   g_cnt[Ee];
__device__ int   g_slot[Ee*Tt];
__device__ float g_topw[NPAIR];
__device__ u16   g_xh[Tt*Dd];            // x as bf16 hi
__device__ u16   g_xl[Tt*Dd];            // x residual lo
__device__ u16   g_Hh[NPAIR*II];         // H bf16 hi
__device__ u16   g_Hl[NPAIR*II];         // H residual lo
__device__ float g_Y[NPAIR*Dd];          // 8 MB

// ---- pipeline geometry ----
#define KC 32                 // k per chunk
#define STG 4
#define AST4 144              // A row stride bytes (fp32, 32 floats + pad)
#define ASZ4 (128*AST4)       // 18432
#define XSTB 80               // X row stride bytes (bf16, 64B data + pad)
#define XSZB (64*XSTB)        // 5120
#define STAGE_SZ (ASZ4 + 2*XSZB)   // 28672
#define SMEM_TOT (STG*STAGE_SZ)    // 114688
#define USTR 65

__device__ __forceinline__ void cvt_hl(float vx, float vy, u32& h, u32& l){
  asm("cvt.rn.bf16x2.f32 %0, %1, %2;" : "=r"(h) : "f"(vy), "f"(vx));
  float r0 = vx - __uint_as_float(h << 16);
  float r1 = vy - __uint_as_float(h & 0xFFFF0000u);
  asm("cvt.rn.bf16x2.f32 %0, %1, %2;" : "=r"(l) : "f"(r1), "f"(r0));
}

__device__ __forceinline__ void mma16816(float* c, const u32* a, u32 b0, u32 b1){
  asm volatile(
    "mma.sync.aligned.m16n8k16.row.col.f32.bf16.bf16.f32 "
    "{%0,%1,%2,%3}, {%4,%5,%6,%7}, {%8,%9}, {%0,%1,%2,%3};"
    : "+f"(c[0]), "+f"(c[1]), "+f"(c[2]), "+f"(c[3])
    : "r"(a[0]), "r"(a[1]), "r"(a[2]), "r"(a[3]), "r"(b0), "r"(b1));
}

__device__ __forceinline__ void ldsm4(u32* r, u32 addr){
  asm volatile("ldmatrix.sync.aligned.m8n8.x4.shared.b16 {%0,%1,%2,%3}, [%4];"
    : "=r"(r[0]), "=r"(r[1]), "=r"(r[2]), "=r"(r[3]) : "r"(addr));
}

__device__ __forceinline__ float2 lds64f(u32 a){
  float2 v; asm volatile("ld.shared.v2.f32 {%0,%1}, [%2];" : "=f"(v.x), "=f"(v.y) : "r"(a));
  return v;
}

__device__ __forceinline__ void cpa16(u32 dst, const void* src){
  asm volatile("cp.async.cg.shared.global [%0], [%1], 16;" :: "r"(dst), "l"(src));
}
#define CPA_COMMIT asm volatile("cp.async.commit_group;" ::: "memory")
#define CPA_WAIT   asm volatile("cp.async.wait_group 2;" ::: "memory")

// build A fragment pair (hi/lo) from fp32 smem tile
__device__ __forceinline__ void afrag(u32 Ast, int wid, int lane, int ks, u32* ah, u32* al){
  int gid = lane >> 2, tig = lane & 3;
  u32 a0 = Ast + (u32)(wid*16 + gid)*AST4 + (u32)(ks*16 + tig*2)*4;
  float2 v00 = lds64f(a0);
  float2 v10 = lds64f(a0 + 8*AST4);
  float2 v01 = lds64f(a0 + 32);
  float2 v11 = lds64f(a0 + 8*AST4 + 32);
  cvt_hl(v00.x, v00.y, ah[0], al[0]);
  cvt_hl(v10.x, v10.y, ah[1], al[1]);
  cvt_hl(v01.x, v01.y, ah[2], al[2]);
  cvt_hl(v11.x, v11.y, ah[3], al[3]);
}

// consume one staged chunk: 2 k16 steps, jpairs n-pairs
__device__ __forceinline__ void consume(float C[8][4], u32 stg, int wid, int lane, int jpairs){
  u32 Ast = stg, Xh = stg + ASZ4, Xl = Xh + XSZB;
  int q = lane >> 3, rr = lane & 7;
  u32 bbase = (u32)(((q >> 1) << 3) + rr)*XSTB + (q & 1)*16;
  #pragma unroll
  for (int ks = 0; ks < 2; ks++){
    u32 ah[4], al[4];
    afrag(Ast, wid, lane, ks, ah, al);
    #pragma unroll
    for (int jp = 0; jp < 4; jp++){
      if (jp >= jpairs) break;
      u32 bh[4], bl[4];
      ldsm4(bh, Xh + bbase + (u32)(jp*16)*XSTB + ks*32);
      ldsm4(bl, Xl + bbase + (u32)(jp*16)*XSTB + ks*32);
      int j0 = jp*2, j1 = jp*2 + 1;
      mma16816(C[j0], ah, bh[0], bh[1]);
      mma16816(C[j1], ah, bh[2], bh[3]);
      mma16816(C[j0], al, bh[0], bh[1]);
      mma16816(C[j1], al, bh[2], bh[3]);
      mma16816(C[j0], ah, bl[0], bl[1]);
      mma16816(C[j1], ah, bl[2], bl[3]);
    }
  }
}

// ---- kernel 0: x -> bf16 hi/lo (+ zero counters) ----
__global__ void cvtx_kernel(const float* __restrict__ x){
  if (blockIdx.x == 0 && threadIdx.x < Ee) g_cnt[threadIdx.x] = 0;
  int i = blockIdx.x*256 + threadIdx.x;       // one float4 per thread
  float4 v = ((const float4*)x)[i];
  u32 h0, l0, h1, l1;
  cvt_hl(v.x, v.y, h0, l0);
  cvt_hl(v.z, v.w, h1, l1);
  ((uint2*)g_xh)[i] = make_uint2(h0, h1);
  ((uint2*)g_xl)[i] = make_uint2(l0, l1);
}

// ---- kernel 1: router ----
__global__ void router_kernel(const float* __restrict__ x, const float* __restrict__ gw){
  int t = blockIdx.x;
  __shared__ float xs[Dd];
  __shared__ float lg[Ee];
  for (int i = threadIdx.x; i < Dd/4; i += 64)
    ((float4*)xs)[i] = ((const float4*)(x + (size_t)t*Dd))[i];
  __syncthreads();
  const float* w = gw + (size_t)threadIdx.x * Dd;
  float acc = 0.f;
  #pragma unroll 4
  for (int d = 0; d < Dd; d += 4){
    float4 wv = *(const float4*)(w + d);
    acc += wv.x*xs[d] + wv.y*xs[d+1] + wv.z*xs[d+2] + wv.w*xs[d+3];
  }
  lg[threadIdx.x] = acc;
  __syncthreads();
  if (threadIdx.x == 0){
    float mx = lg[0];
    for (int i = 1; i < Ee; i++) mx = fmaxf(mx, lg[i]);
    for (int i = 0; i < Ee; i++) lg[i] = __expf(lg[i] - mx);
    float wsum = 0.f; int ids[KK]; float ws[KK];
    for (int k = 0; k < KK; k++){
      int bi = 0; float bv = -1.f;
      for (int i = 0; i < Ee; i++){ float v = lg[i]; if (v > bv){ bv = v; bi = i; } }
      ids[k] = bi; ws[k] = bv; lg[bi] = -2.f; wsum += bv;
    }
    float inv = 1.f / wsum;
    for (int k = 0; k < KK; k++){
      int p = t*KK + k;
      g_topw[p] = ws[k] * inv;
      int slot = atomicAdd(&g_cnt[ids[k]], 1);
      g_slot[ids[k]*Tt + slot] = p;
    }
  }
}

// ---- kernel 2: gate+up GEMM (cp.async pipeline, line-coalesced A) ----
// grid (Ee, 8). A rows 0-63 = gate f0.., 64-127 = up f0..; warps 0-3 gate, 4-7 up.
__global__ void __launch_bounds__(256,2) gateup_kernel(
    const float* __restrict__ wg, const float* __restrict__ wu){
  int e = blockIdx.x;
  int nt = g_cnt[e];
  if (nt == 0) return;
  int f0 = blockIdx.y * 64;
  extern __shared__ char dsm[];
  __shared__ int sp[64];
  int tid = threadIdx.x, wid = tid >> 5, lane = tid & 31;
  int gid = lane >> 2, tig = lane & 3;
  u32 sb = (u32)__cvta_generic_to_shared(dsm);
  float* ub = (float*)dsm;

  // A staging map: j-th op covers rows j*32 + (tid>>3); 8 consecutive threads = one row's 128B
  int r0 = tid >> 3, seg = tid & 7;
  const float* ap[4];
  ap[0] = wg + ((size_t)e*II + f0 + r0)*Dd + seg*4;
  ap[1] = ap[0] + (size_t)32*Dd;
  ap[2] = wu + ((size_t)e*II + f0 + r0)*Dd + seg*4;
  ap[3] = ap[2] + (size_t)32*Dd;
  u32 adst[4];
  #pragma unroll
  for (int j = 0; j < 4; j++) adst[j] = (u32)(j*32 + r0)*AST4 + (u32)seg*16;

  int xrow = tid >> 2, xseg = tid & 3;
  u32 xdst = (u32)xrow*XSTB + (u32)xseg*16;

  for (int n0 = 0; n0 < nt; n0 += 64){
    int ntile = min(64, nt - n0), nfr = (ntile + 7) >> 3;
    int jpairs = (nfr + 1) >> 1;
    __syncthreads();
    if (tid < 64) sp[tid] = g_slot[e*Tt + ((n0 + tid < nt) ? n0 + tid : n0)];
    __syncthreads();
    const u16* xhPtr = g_xh + (size_t)(sp[xrow] >> 2)*Dd + xseg*8;
    const u16* xlPtr = g_xl + (size_t)(sp[xrow] >> 2)*Dd + xseg*8;

    float C[8][4];
    #pragma unroll
    for (int j = 0; j < 8; j++){ C[j][0]=C[j][1]=C[j][2]=C[j][3]=0.f; }

    #pragma unroll
    for (int s = 0; s < STG-1; s++){
      u32 st = sb + s*STAGE_SZ;
      #pragma unroll
      for (int j = 0; j < 4; j++) cpa16(st + adst[j], ap[j] + s*KC);
      cpa16(st + ASZ4 + xdst,        xhPtr + s*KC);
      cpa16(st + ASZ4 + XSZB + xdst, xlPtr + s*KC);
      CPA_COMMIT;
    }
    for (int c = 0; c < Dd/KC; c++){
      CPA_WAIT;
      __syncthreads();
      int cn = c + STG - 1;
      if (cn < Dd/KC){
        u32 st = sb + (cn % STG)*STAGE_SZ;
        #pragma unroll
        for (int j = 0; j < 4; j++) cpa16(st + adst[j], ap[j] + cn*KC);
        cpa16(st + ASZ4 + xdst,        xhPtr + cn*KC);
        cpa16(st + ASZ4 + XSZB + xdst, xlPtr + cn*KC);
      }
      CPA_COMMIT;
      consume(C, sb + (c % STG)*STAGE_SZ, wid, lane, jpairs);
    }

    __syncthreads();
    if (wid >= 4){
      #pragma unroll
      for (int j = 0; j < 8; j++) if (j < nfr)
        #pragma unroll
        for (int q = 0; q < 4; q++){
          int row = (wid-4)*16 + gid + ((q>>1)<<3);
          int col = j*8 + tig*2 + (q&1);
          ub[row*USTR + col] = C[j][q];
        }
    }
    __syncthreads();
    if (wid < 4){
      #pragma unroll
      for (int j = 0; j < 8; j++) if (j < nfr)
        #pragma unroll
        for (int q = 0; q < 4; q++){
          int cc = j*8 + tig*2 + (q&1);
          if (cc < ntile){
            int rl = wid*16 + gid + ((q>>1)<<3);
            float g = C[j][q], u = ub[rl*USTR + cc];
            float h = (g / (1.f + __expf(-g))) * u;
            u16 hs; asm("cvt.rn.bf16.f32 %0, %1;" : "=h"(hs) : "f"(h));
            float lo = h - __uint_as_float(((u32)hs) << 16);
            u16 ls; asm("cvt.rn.bf16.f32 %0, %1;" : "=h"(ls) : "f"(lo));
            size_t idx = (size_t)sp[cc]*II + f0 + rl;
            g_Hh[idx] = hs;
            g_Hl[idx] = ls;
          }
        }
    }
    __syncthreads();   // ub reuse vs next n0 staging
  }
}

// ---- kernel 3: down GEMM (cp.async pipeline, line-coalesced A) ----
// grid (Ee, 8): 128 d-rows per block, K=512.
__global__ void __launch_bounds__(256,2) down_kernel(const float* __restrict__ wd){
  int e = blockIdx.x;
  int nt = g_cnt[e];
  if (nt == 0) return;
  int d0 = blockIdx.y * 128;
  extern __shared__ char dsm[];
  __shared__ int sp[64];
  int tid = threadIdx.x, wid = tid >> 5, lane = tid & 31;
  int gid = lane >> 2, tig = lane & 3;
  u32 sb = (u32)__cvta_generic_to_shared(dsm);

  int r0 = tid >> 3, seg = tid & 7;
  const float* ap[4];
  u32 adst[4];
  #pragma unroll
  for (int j = 0; j < 4; j++){
    ap[j] = wd + ((size_t)e*Dd + d0 + j*32 + r0)*II + seg*4;
    adst[j] = (u32)(j*32 + r0)*AST4 + (u32)seg*16;
  }
  int xrow = tid >> 2, xseg = tid & 3;
  u32 xdst = (u32)xrow*XSTB + (u32)xseg*16;

  for (int n0 = 0; n0 < nt; n0 += 64){
    int ntile = min(64, nt - n0), nfr = (ntile + 7) >> 3;
    int jpairs = (nfr + 1) >> 1;
    __syncthreads();
    if (tid < 64) sp[tid] = g_slot[e*Tt + ((n0 + tid < nt) ? n0 + tid : n0)];
    __syncthreads();
    const u16* xhPtr = g_Hh + (size_t)sp[xrow]*II + xseg*8;
    const u16* xlPtr = g_Hl + (size_t)sp[xrow]*II + xseg*8;

    float C[8][4];
    #pragma unroll
    for (int j = 0; j < 8; j++){ C[j][0]=C[j][1]=C[j][2]=C[j][3]=0.f; }

    #pragma unroll
    for (int s = 0; s < STG-1; s++){
      u32 st = sb + s*STAGE_SZ;
      #pragma unroll
      for (int j = 0; j < 4; j++) cpa16(st + adst[j], ap[j] + s*KC);
      cpa16(st + ASZ4 + xdst,        xhPtr + s*KC);
      cpa16(st + ASZ4 + XSZB + xdst, xlPtr + s*KC);
      CPA_COMMIT;
    }
    for (int c = 0; c < II/KC; c++){
      CPA_WAIT;
      __syncthreads();
      int cn = c + STG - 1;
      if (cn < II/KC){
        u32 st = sb + (cn % STG)*STAGE_SZ;
        #pragma unroll
        for (int j = 0; j < 4; j++) cpa16(st + adst[j], ap[j] + cn*KC);
        cpa16(st + ASZ4 + xdst,        xhPtr + cn*KC);
        cpa16(st + ASZ4 + XSZB + xdst, xlPtr + cn*KC);
      }
      CPA_COMMIT;
      consume(C, sb + (c % STG)*STAGE_SZ, wid, lane, jpairs);
    }

    int drow = d0 + wid*16 + gid;
    #pragma unroll
    for (int j = 0; j < 8; j++) if (j < nfr)
      #pragma unroll
      for (int q = 0; q < 4; q++){
        int cc = j*8 + tig*2 + (q&1);
        if (cc < ntile)
          g_Y[(size_t)sp[cc]*Dd + drow + ((q>>1)<<3)] = C[j][q];
      }
  }
}

// ---- kernel 4: combine ----
__global__ void combine_kernel(float* __restrict__ out){
  int t = blockIdx.x;
  int i = threadIdx.x;
  float w0 = g_topw[t*4+0], w1 = g_topw[t*4+1];
  float w2 = g_topw[t*4+2], w3 = g_topw[t*4+3];
  const float4* y0 = (const float4*)(g_Y + (size_t)(t*4+0)*Dd);
  const float4* y1 = (const float4*)(g_Y + (size_t)(t*4+1)*Dd);
  const float4* y2 = (const float4*)(g_Y + (size_t)(t*4+2)*Dd);
  const float4* y3 = (const float4*)(g_Y + (size_t)(t*4+3)*Dd);
  float4 a = y0[i], b = y1[i], c = y2[i], d = y3[i];
  float4 r;
  r.x = w0*a.x + w1*b.x + w2*c.x + w3*d.x;
  r.y = w0*a.y + w1*b.y + w2*c.y + w3*d.y;
  r.z = w0*a.z + w1*b.z + w2*c.z + w3*d.z;
  r.w = w0*a.w + w1*b.w + w2*c.w + w3*d.w;
  ((float4*)(out + (size_t)t*Dd))[i] = r;
}

extern "C" void kernel_launch(void* const* d_in, const int* in_sizes, int n_in,
                              void* d_out, int out_size){
  const float* x  = (const float*)d_in[0];
  const float* gw = (const float*)d_in[1];
  const float* wg = (const float*)d_in[2];
  const float* wu = (const float*)d_in[3];
  const float* wd = (const float*)d_in[4];
  float* out = (float*)d_out;
  (void)in_sizes; (void)n_in; (void)out_size;

  static int inited = 0;
  if (!inited){
    cudaFuncSetAttribute(gateup_kernel, cudaFuncAttributeMaxDynamicSharedMemorySize, SMEM_TOT);
    cudaFuncSetAttribute(down_kernel,   cudaFuncAttributeMaxDynamicSharedMemorySize, SMEM_TOT);
    inited = 1;
  }

  cvtx_kernel<<<Tt, 256>>>(x);
  router_kernel<<<Tt, 64>>>(x, gw);
  gateup_kernel<<<dim3(Ee, 8), 256, SMEM_TOT>>>(wg, wu);
  down_kernel<<<dim3(Ee, 8), 256, SMEM_TOT>>>(wd);
  combine_kernel<<<Tt, 256>>>(out);
}